// round 6
// baseline (speedup 1.0000x reference)
#include <cuda_runtime.h>
#include <cstdint>

// Problem dims
#define B_N 64
#define T_T 512
#define V_V 25
#define C_IN 3
#define C_H 64
#define F_F 25
#define G_G 100   // 4*F

// Scratch (device globals; no allocation allowed)
__device__ float g_zx[(size_t)T_T * B_N * V_V * G_G];   // [t][n][v][g]
__device__ float g_hs[(size_t)B_N * T_T * V_V * F_F];   // [n][t][v][f]

__device__ __forceinline__ uint32_t f2tf32(float f) {
    uint32_t u;
    asm("cvt.rna.tf32.f32 %0, %1;" : "=r"(u) : "f"(f));
    return u;
}

__device__ __forceinline__ void mma_tf32(float* d, const uint32_t* a, const uint32_t* b) {
    asm volatile(
        "mma.sync.aligned.m16n8k8.row.col.f32.tf32.tf32.f32 "
        "{%0,%1,%2,%3}, {%4,%5,%6,%7}, {%8,%9}, {%0,%1,%2,%3};\n"
        : "+f"(d[0]), "+f"(d[1]), "+f"(d[2]), "+f"(d[3])
        : "r"(a[0]), "r"(a[1]), "r"(a[2]), "r"(a[3]), "r"(b[0]), "r"(b[1]));
}

// Packed dual-lane fp32 FMA (Blackwell f32x2) — exact fp32 per lane.
__device__ __forceinline__ float2 ffma2(float2 a, float2 b, float2 c) {
    float2 d;
    asm("fma.rn.f32x2 %0, %1, %2, %3;"
        : "=l"(reinterpret_cast<unsigned long long&>(d))
        : "l"(reinterpret_cast<unsigned long long&>(a)),
          "l"(reinterpret_cast<unsigned long long&>(b)),
          "l"(reinterpret_cast<unsigned long long&>(c)));
    return d;
}

__device__ __forceinline__ float hsig(float x) {
    return __saturatef(fmaf(0.2f, x, 0.5f));
}

// ---------------------------------------------------------------------------
// Kernel 1: zx[t,n,v,:] = relu(x[n,t,v,:] @ Wc + bc) @ Wl + bl
// tf32 mma with hi/lo split (3 MMAs). B hi/lo precomputed ONCE in smem
// (interleaved float2) so the inner loop is pure LDS.64 + MMA.
// ---------------------------------------------------------------------------
__global__ __launch_bounds__(128) void k_zx(
    const float* __restrict__ x, const float* __restrict__ Wc,
    const float* __restrict__ bc, const float* __restrict__ Wl,
    const float* __restrict__ bl)
{
    __shared__ float2 s_B2[64 * 104];   // {hi, lo} per element; cols 100..103 zero
    const int tid = threadIdx.x;

    for (int i = tid; i < 64 * 104; i += 128) {
        int k = i / 104, n = i - (i / 104) * 104;
        float b = (n < G_G) ? Wl[k * G_G + n] : 0.f;
        float bh = __uint_as_float(f2tf32(b));
        s_B2[i] = make_float2(bh, b - bh);
    }
    __syncthreads();

    const int lane = tid & 31, warp = tid >> 5;
    const int gid = lane >> 2;      // groupID
    const int tig = lane & 3;       // threadID in group
    const int rloc0 = warp * 16 + gid;
    const int r0 = blockIdx.x * 64 + rloc0;
    const int r1 = r0 + 8;

    const float x00 = __ldg(x + r0 * 3), x01 = __ldg(x + r0 * 3 + 1), x02 = __ldg(x + r0 * 3 + 2);
    const float x10 = __ldg(x + r1 * 3), x11 = __ldg(x + r1 * 3 + 1), x12 = __ldg(x + r1 * 3 + 2);

    float acc[13][4];
#pragma unroll
    for (int i = 0; i < 13; i++)
#pragma unroll
        for (int j = 0; j < 4; j++) acc[i][j] = 0.f;

#pragma unroll
    for (int kt = 0; kt < 8; kt++) {
        const int c0 = kt * 8 + tig, c1 = c0 + 4;
        float a00 = fmaxf(fmaf(x02, __ldg(Wc + 128 + c0), fmaf(x01, __ldg(Wc + 64 + c0), fmaf(x00, __ldg(Wc + c0), __ldg(bc + c0)))), 0.f);
        float a10 = fmaxf(fmaf(x12, __ldg(Wc + 128 + c0), fmaf(x11, __ldg(Wc + 64 + c0), fmaf(x10, __ldg(Wc + c0), __ldg(bc + c0)))), 0.f);
        float a01 = fmaxf(fmaf(x02, __ldg(Wc + 128 + c1), fmaf(x01, __ldg(Wc + 64 + c1), fmaf(x00, __ldg(Wc + c1), __ldg(bc + c1)))), 0.f);
        float a11 = fmaxf(fmaf(x12, __ldg(Wc + 128 + c1), fmaf(x11, __ldg(Wc + 64 + c1), fmaf(x10, __ldg(Wc + c1), __ldg(bc + c1)))), 0.f);

        uint32_t ah[4], al[4];
        ah[0] = f2tf32(a00); al[0] = __float_as_uint(a00 - __uint_as_float(ah[0]));
        ah[1] = f2tf32(a10); al[1] = __float_as_uint(a10 - __uint_as_float(ah[1]));
        ah[2] = f2tf32(a01); al[2] = __float_as_uint(a01 - __uint_as_float(ah[2]));
        ah[3] = f2tf32(a11); al[3] = __float_as_uint(a11 - __uint_as_float(ah[3]));

        const float2* brow0 = s_B2 + (kt * 8 + tig) * 104 + gid;
        const float2* brow1 = brow0 + 4 * 104;
#pragma unroll
        for (int nt = 0; nt < 13; nt++) {
            float2 b0 = brow0[nt * 8];
            float2 b1 = brow1[nt * 8];
            uint32_t bh[2], blo[2];
            bh[0] = __float_as_uint(b0.x); blo[0] = __float_as_uint(b0.y);
            bh[1] = __float_as_uint(b1.x); blo[1] = __float_as_uint(b1.y);
            mma_tf32(acc[nt], ah, bh);    // hi*hi
            mma_tf32(acc[nt], ah, blo);   // hi*lo
            mma_tf32(acc[nt], al, bh);    // lo*hi
        }
    }

    __syncthreads();   // all reads of s_B2 done; reuse as fp32 staging
    float* s_stage = (float*)s_B2;   // 64 rows x 104 cols
#pragma unroll
    for (int nt = 0; nt < 13; nt++) {
        const int cc = nt * 8 + 2 * tig;
        s_stage[rloc0 * 104 + cc]           = acc[nt][0];
        s_stage[rloc0 * 104 + cc + 1]       = acc[nt][1];
        s_stage[(rloc0 + 8) * 104 + cc]     = acc[nt][2];
        s_stage[(rloc0 + 8) * 104 + cc + 1] = acc[nt][3];
    }
    __syncthreads();

    // Epilogue: 2 threads per row, 50 contiguous floats each (float2 stores).
    {
        const int r = tid >> 1;
        const int half = tid & 1;          // 0: g in [0,50), 1: g in [50,100)
        const int p = blockIdx.x * 64 + r; // p = (n*T + t)*V + v
        const int n = p / (T_T * V_V);
        const int rem = p - n * (T_T * V_V);
        const int t = rem / V_V;
        const int v = rem - t * V_V;
        const int g0 = half * 50;
        float* dst = g_zx + ((size_t)(t * B_N + n) * V_V + v) * G_G + g0;
        const float* src = s_stage + r * 104 + g0;
        const float* blp = bl + g0;
#pragma unroll
        for (int q = 0; q < 25; q++) {
            float2 val = make_float2(src[2 * q] + __ldg(blp + 2 * q),
                                     src[2 * q + 1] + __ldg(blp + 2 * q + 1));
            *reinterpret_cast<float2*>(dst + 2 * q) = val;
        }
    }
}

// ---------------------------------------------------------------------------
// Kernel 2: LSTM recurrence. One block per (n,v) cell. Thread g<100 owns gate
// output g and keeps U[:,g] in 25 registers (as 12 float2 pairs + 1 scalar).
// h broadcast via LDS.128; matvec via packed FFMA2. z prefetched 1 step ahead.
// ---------------------------------------------------------------------------
__global__ __launch_bounds__(128) void k_rec(const float* __restrict__ U)
{
    __shared__ float4 s_h4[7];     // h[0..24], padded to 28
    __shared__ float s_g[G_G];

    const int tid = threadIdx.x;
    const int n = blockIdx.x / V_V;
    const int v = blockIdx.x % V_V;

    float2 u2[12];
    float u24 = 0.f;
    if (tid < G_G) {
#pragma unroll
        for (int q = 0; q < 12; q++)
            u2[q] = make_float2(__ldg(U + (2 * q) * G_G + tid),
                                __ldg(U + (2 * q + 1) * G_G + tid));
        u24 = __ldg(U + 24 * G_G + tid);
    }
    if (tid < 7) s_h4[tid] = make_float4(0.f, 0.f, 0.f, 0.f);
    __syncthreads();

    const size_t zstride = (size_t)B_N * V_V * G_G;
    const float* zxp = g_zx + (size_t)(n * V_V + v) * G_G + tid;
    float* hp = g_hs + (size_t)n * T_T * V_V * F_F + (size_t)v * F_F + tid;

    float c = 0.f;
    float z = (tid < G_G) ? zxp[0] : 0.f;

    for (int t = 0; t < T_T; t++) {
        float z_next = 0.f;
        if (tid < G_G && t + 1 < T_T) z_next = zxp[(size_t)(t + 1) * zstride];  // prefetch

        if (tid < G_G) {
            float2 acc2 = make_float2(z, 0.f);
#pragma unroll
            for (int q = 0; q < 6; q++) {
                float4 h = s_h4[q];
                acc2 = ffma2(make_float2(h.x, h.y), u2[2 * q], acc2);
                acc2 = ffma2(make_float2(h.z, h.w), u2[2 * q + 1], acc2);
            }
            float h24 = s_h4[6].x;
            s_g[tid] = fmaf(h24, u24, acc2.x + acc2.y);
        }
        __syncthreads();   // s_g complete

        if (tid < F_F) {
            float gi = s_g[tid];
            float gf = s_g[F_F + tid];
            float gg = s_g[2 * F_F + tid];
            float go = s_g[3 * F_F + tid];
            c = hsig(gf) * c + hsig(gi) * tanhf(gg);
            float h = hsig(go) * tanhf(c);
            ((float*)s_h4)[tid] = h;
            hp[(size_t)t * (V_V * F_F)] = h;
        }
        z = z_next;
        __syncthreads();   // s_h ready for next step
    }
}

// ---------------------------------------------------------------------------
// Kernel 3: softmax attention + aggregation, one block per (n,t).
// x1 recomputed from x; aggregation via float4 loads + FFMA2.
// ---------------------------------------------------------------------------
__global__ __launch_bounds__(256) void k_agg(
    const float* __restrict__ x, const float* __restrict__ Wc,
    const float* __restrict__ bc, const float* __restrict__ bias,
    float* __restrict__ out)
{
    __shared__ float4 s_x14[V_V * 16];   // x1: 25 x 64 as float4
    __shared__ float s_hr[V_V * F_F];
    __shared__ float s_co[V_V * F_F];

    const int b = blockIdx.x;            // n*T + t
    const int tid = threadIdx.x;

    const float* xp = x + (size_t)b * V_V * C_IN;
    float* s_x1 = (float*)s_x14;
    for (int i = tid; i < V_V * C_H; i += 256) {
        int v = i >> 6, cch = i & 63;
        float val = fmaf(xp[v * 3 + 2], __ldg(Wc + 128 + cch),
                    fmaf(xp[v * 3 + 1], __ldg(Wc + 64 + cch),
                    fmaf(xp[v * 3 + 0], __ldg(Wc + cch), __ldg(bc + cch))));
        s_x1[i] = fmaxf(val, 0.f);
    }
    const float* hpp = g_hs + (size_t)b * (V_V * F_F);
    for (int i = tid; i < V_V * F_F; i += 256) s_hr[i] = hpp[i];
    __syncthreads();

    if (tid < V_V) {
        const int v = tid;
        float l[F_F];
        float mx = -1e30f;
#pragma unroll
        for (int w = 0; w < F_F; w++) {
            float h = s_hr[v * F_F + w];
            float lv = (h > 0.f ? h : 0.2f * h) + __ldg(bias + v * V_V + w);
            l[w] = lv;
            mx = fmaxf(mx, lv);
        }
        float s = 0.f;
#pragma unroll
        for (int w = 0; w < F_F; w++) {
            float e = __expf(l[w] - mx);
            l[w] = e;
            s += e;
        }
        float inv = 1.f / s;
#pragma unroll
        for (int w = 0; w < F_F; w++) s_co[v * F_F + w] = l[w] * inv;
    }
    __syncthreads();

    float* op = out + (size_t)b * V_V * C_H;
    for (int i = tid; i < V_V * 16; i += 256) {
        int v = i >> 4, c4 = i & 15;
        float2 a01 = make_float2(0.f, 0.f);
        float2 a23 = make_float2(0.f, 0.f);
#pragma unroll
        for (int w = 0; w < F_F; w++) {
            float co = s_co[v * F_F + w];
            float4 xv = s_x14[w * 16 + c4];
            a01 = ffma2(make_float2(co, co), make_float2(xv.x, xv.y), a01);
            a23 = ffma2(make_float2(co, co), make_float2(xv.z, xv.w), a23);
        }
        float4 r = make_float4(a01.x, a01.y, a23.x, a23.y);
        *reinterpret_cast<float4*>(op + v * C_H + c4 * 4) = r;
    }
}

// ---------------------------------------------------------------------------
extern "C" void kernel_launch(void* const* d_in, const int* in_sizes, int n_in,
                              void* d_out, int out_size)
{
    const float* x    = (const float*)d_in[0];   // (64,512,25,3)
    const float* Wc   = (const float*)d_in[1];   // (3,64)
    const float* bc   = (const float*)d_in[2];   // (64,)
    const float* Wl   = (const float*)d_in[3];   // (64,100)
    const float* Ul   = (const float*)d_in[4];   // (25,100)
    const float* bl   = (const float*)d_in[5];   // (100,)
    const float* bias = (const float*)d_in[6];   // (25,25)
    float* out = (float*)d_out;                  // (64,512,25,64)

    k_zx<<<(B_N * T_T * V_V) / 64, 128>>>(x, Wc, bc, Wl, bl);
    k_rec<<<B_N * V_V, 128>>>(Ul);
    k_agg<<<B_N * T_T, 256>>>(x, Wc, bc, bias, out);
}

// round 10
// speedup vs baseline: 1.4109x; 1.4109x over previous
#include <cuda_runtime.h>
#include <cstdint>

// Problem dims
#define B_N 64
#define T_T 512
#define V_V 25
#define C_IN 3
#define C_H 64
#define F_F 25
#define G_G 100   // 4*F

// Scratch (device globals; no allocation allowed)
__device__ float g_zx[(size_t)T_T * B_N * V_V * G_G];   // [t][n][v][g]
__device__ float g_hs[(size_t)B_N * T_T * V_V * F_F];   // [n][t][v][f]

__device__ __forceinline__ uint32_t f2tf32(float f) {
    uint32_t u;
    asm("cvt.rna.tf32.f32 %0, %1;" : "=r"(u) : "f"(f));
    return u;
}

__device__ __forceinline__ void mma_tf32(float* d, const uint32_t* a, const uint32_t* b) {
    asm volatile(
        "mma.sync.aligned.m16n8k8.row.col.f32.tf32.tf32.f32 "
        "{%0,%1,%2,%3}, {%4,%5,%6,%7}, {%8,%9}, {%0,%1,%2,%3};\n"
        : "+f"(d[0]), "+f"(d[1]), "+f"(d[2]), "+f"(d[3])
        : "r"(a[0]), "r"(a[1]), "r"(a[2]), "r"(a[3]), "r"(b[0]), "r"(b[1]));
}

__device__ __forceinline__ float hsig(float x) {
    return __saturatef(fmaf(0.2f, x, 0.5f));
}

// ---------------------------------------------------------------------------
// Kernel 1: zx[t,n,v,:] = relu(x[n,t,v,:] @ Wc + bc) @ Wl + bl
// (R1 version, measured 344us: scalar smem B, inline cvt hi/lo split, 3 MMAs)
// ---------------------------------------------------------------------------
__global__ __launch_bounds__(128) void k_zx(
    const float* __restrict__ x, const float* __restrict__ Wc,
    const float* __restrict__ bc, const float* __restrict__ Wl,
    const float* __restrict__ bl)
{
    __shared__ float s_B[64 * 104];   // W_lstm, zero-padded cols 100..103; reused as epilogue staging
    const int tid = threadIdx.x;

    for (int i = tid; i < 64 * 104; i += 128) {
        int k = i / 104, n = i - (i / 104) * 104;
        s_B[i] = (n < G_G) ? Wl[k * G_G + n] : 0.f;
    }
    __syncthreads();

    const int lane = tid & 31, warp = tid >> 5;
    const int gid = lane >> 2;      // groupID
    const int tig = lane & 3;       // threadID in group
    const int rloc0 = warp * 16 + gid;
    const int r0 = blockIdx.x * 64 + rloc0;
    const int r1 = r0 + 8;

    const float x00 = x[r0 * 3 + 0], x01 = x[r0 * 3 + 1], x02 = x[r0 * 3 + 2];
    const float x10 = x[r1 * 3 + 0], x11 = x[r1 * 3 + 1], x12 = x[r1 * 3 + 2];

    float acc[13][4];
#pragma unroll
    for (int i = 0; i < 13; i++) {
#pragma unroll
        for (int j = 0; j < 4; j++) acc[i][j] = 0.f;
    }

#pragma unroll
    for (int kt = 0; kt < 8; kt++) {
        const int c0 = kt * 8 + tig, c1 = c0 + 4;
        // A fragment: x1 = relu(x @ Wc + bc), computed on the fly
        float a00 = fmaxf(fmaf(x02, Wc[128 + c0], fmaf(x01, Wc[64 + c0], fmaf(x00, Wc[c0], bc[c0]))), 0.f);
        float a10 = fmaxf(fmaf(x12, Wc[128 + c0], fmaf(x11, Wc[64 + c0], fmaf(x10, Wc[c0], bc[c0]))), 0.f);
        float a01 = fmaxf(fmaf(x02, Wc[128 + c1], fmaf(x01, Wc[64 + c1], fmaf(x00, Wc[c1], bc[c1]))), 0.f);
        float a11 = fmaxf(fmaf(x12, Wc[128 + c1], fmaf(x11, Wc[64 + c1], fmaf(x10, Wc[c1], bc[c1]))), 0.f);

        uint32_t ah[4], al[4];
        ah[0] = f2tf32(a00); al[0] = __float_as_uint(a00 - __uint_as_float(ah[0]));
        ah[1] = f2tf32(a10); al[1] = __float_as_uint(a10 - __uint_as_float(ah[1]));
        ah[2] = f2tf32(a01); al[2] = __float_as_uint(a01 - __uint_as_float(ah[2]));
        ah[3] = f2tf32(a11); al[3] = __float_as_uint(a11 - __uint_as_float(ah[3]));

        const int br0 = (kt * 8 + tig) * 104 + gid;
        const int br1 = (kt * 8 + tig + 4) * 104 + gid;
#pragma unroll
        for (int nt = 0; nt < 13; nt++) {
            float b0f = s_B[br0 + nt * 8];
            float b1f = s_B[br1 + nt * 8];
            uint32_t bh[2], blo[2];
            bh[0] = f2tf32(b0f); blo[0] = __float_as_uint(b0f - __uint_as_float(bh[0]));
            bh[1] = f2tf32(b1f); blo[1] = __float_as_uint(b1f - __uint_as_float(bh[1]));
            mma_tf32(acc[nt], ah, bh);    // hi*hi
            mma_tf32(acc[nt], ah, blo);   // hi*lo
            mma_tf32(acc[nt], al, bh);    // lo*hi  (lo*lo ~2^-22, negligible)
        }
    }

    __syncthreads();   // everyone done reading s_B; reuse as output staging
#pragma unroll
    for (int nt = 0; nt < 13; nt++) {
        const int cc = nt * 8 + 2 * tig;
        s_B[rloc0 * 104 + cc]           = acc[nt][0];
        s_B[rloc0 * 104 + cc + 1]       = acc[nt][1];
        s_B[(rloc0 + 8) * 104 + cc]     = acc[nt][2];
        s_B[(rloc0 + 8) * 104 + cc + 1] = acc[nt][3];
    }
    __syncthreads();

    const int pbase = blockIdx.x * 64;
    for (int i = tid; i < 64 * G_G; i += 128) {
        int r = i / G_G, g = i - r * G_G;
        int p = pbase + r;                       // p = (n*T + t)*V + v
        int n = p / (T_T * V_V);
        int t = (p / V_V) % T_T;
        int v = p % V_V;
        g_zx[((size_t)(t * B_N + n) * V_V + v) * G_G + g] = s_B[r * 104 + g] + bl[g];
    }
}

// ---------------------------------------------------------------------------
// Kernel 2: LSTM recurrence. One block per (n,v) cell. Thread g<100 owns gate
// output g; U[:,g] held in 25 registers (loaded once). h broadcast via
// LDS.128 (float4) — ~40 smem wavefronts per block-step vs ~200 for the
// all-smem version. Scalar fmaf only (no f32x2 packing). z prefetched 1 step.
// ---------------------------------------------------------------------------
__global__ __launch_bounds__(128) void k_rec(const float* __restrict__ U)
{
    __shared__ float4 s_h4[8];     // h[0..24], padded to 32 floats
    __shared__ float s_g[G_G];

    const int tid = threadIdx.x;
    const int n = blockIdx.x / V_V;
    const int v = blockIdx.x % V_V;

    float u[F_F];
    if (tid < G_G) {
#pragma unroll
        for (int j = 0; j < F_F; j++)
            u[j] = __ldg(U + j * G_G + tid);
    }
    if (tid < 8) s_h4[tid] = make_float4(0.f, 0.f, 0.f, 0.f);
    __syncthreads();

    const size_t zstride = (size_t)B_N * V_V * G_G;
    const float* zxp = g_zx + (size_t)(n * V_V + v) * G_G + tid;
    float* hp = g_hs + (size_t)n * T_T * V_V * F_F + (size_t)v * F_F + tid;

    float c = 0.f;
    float z = (tid < G_G) ? zxp[0] : 0.f;

    for (int t = 0; t < T_T; t++) {
        float z_next = 0.f;
        if (tid < G_G && t + 1 < T_T) z_next = zxp[(size_t)(t + 1) * zstride];  // prefetch

        if (tid < G_G) {
            float acc = z;
#pragma unroll
            for (int q = 0; q < 6; q++) {
                float4 h = s_h4[q];                  // broadcast LDS.128
                acc = fmaf(h.x, u[4 * q + 0], acc);
                acc = fmaf(h.y, u[4 * q + 1], acc);
                acc = fmaf(h.z, u[4 * q + 2], acc);
                acc = fmaf(h.w, u[4 * q + 3], acc);
            }
            acc = fmaf(s_h4[6].x, u[24], acc);
            s_g[tid] = acc;
        }
        __syncthreads();   // s_g complete

        if (tid < F_F) {
            float gi = s_g[tid];
            float gf = s_g[F_F + tid];
            float gg = s_g[2 * F_F + tid];
            float go = s_g[3 * F_F + tid];
            c = hsig(gf) * c + hsig(gi) * tanhf(gg);
            float h = hsig(go) * tanhf(c);
            ((float*)s_h4)[tid] = h;
            hp[(size_t)t * (V_V * F_F)] = h;
        }
        z = z_next;
        __syncthreads();   // s_h ready for next step
    }
}

// ---------------------------------------------------------------------------
// Kernel 3: attention softmax + aggregation, one block per (n,t).
// (R1 version.) x1 recomputed from x.
// ---------------------------------------------------------------------------
__global__ __launch_bounds__(256) void k_agg(
    const float* __restrict__ x, const float* __restrict__ Wc,
    const float* __restrict__ bc, const float* __restrict__ bias,
    float* __restrict__ out)
{
    __shared__ float s_x1[V_V * C_H];    // 25 x 64
    __shared__ float s_hr[V_V * F_F];    // 25 x 25
    __shared__ float s_co[V_V * F_F];    // coefs

    const int b = blockIdx.x;            // n*T + t
    const int tid = threadIdx.x;

    const float* xp = x + (size_t)b * V_V * C_IN;
    for (int i = tid; i < V_V * C_H; i += 256) {
        int v = i >> 6, cch = i & 63;
        float val = fmaf(xp[v * 3 + 2], Wc[128 + cch],
                    fmaf(xp[v * 3 + 1], Wc[64 + cch],
                    fmaf(xp[v * 3 + 0], Wc[cch], bc[cch])));
        s_x1[i] = fmaxf(val, 0.f);
    }
    const float* hpp = g_hs + (size_t)b * (V_V * F_F);
    for (int i = tid; i < V_V * F_F; i += 256) s_hr[i] = hpp[i];
    __syncthreads();

    if (tid < V_V) {
        const int v = tid;
        float mx = -1e30f;
#pragma unroll
        for (int w = 0; w < F_F; w++) {
            float h = s_hr[v * F_F + w];
            float l = (h > 0.f ? h : 0.2f * h) + bias[v * V_V + w];
            s_co[v * F_F + w] = l;
            mx = fmaxf(mx, l);
        }
        float s = 0.f;
#pragma unroll
        for (int w = 0; w < F_F; w++) {
            float e = expf(s_co[v * F_F + w] - mx);
            s_co[v * F_F + w] = e;
            s += e;
        }
        float inv = 1.f / s;
#pragma unroll
        for (int w = 0; w < F_F; w++) s_co[v * F_F + w] *= inv;
    }
    __syncthreads();

    float* op = out + (size_t)b * V_V * C_H;
    for (int i = tid; i < V_V * C_H; i += 256) {
        int v = i >> 6, cch = i & 63;
        float acc = 0.f;
#pragma unroll
        for (int w = 0; w < F_F; w++)
            acc = fmaf(s_co[v * F_F + w], s_x1[w * C_H + cch], acc);
        op[i] = acc;
    }
}

// ---------------------------------------------------------------------------
extern "C" void kernel_launch(void* const* d_in, const int* in_sizes, int n_in,
                              void* d_out, int out_size)
{
    const float* x    = (const float*)d_in[0];   // (64,512,25,3)
    const float* Wc   = (const float*)d_in[1];   // (3,64)
    const float* bc   = (const float*)d_in[2];   // (64,)
    const float* Wl   = (const float*)d_in[3];   // (64,100)
    const float* Ul   = (const float*)d_in[4];   // (25,100)
    const float* bl   = (const float*)d_in[5];   // (100,)
    const float* bias = (const float*)d_in[6];   // (25,25)
    float* out = (float*)d_out;                  // (64,512,25,64)

    k_zx<<<(B_N * T_T * V_V) / 64, 128>>>(x, Wc, bc, Wl, bl);
    k_rec<<<B_N * V_V, 128>>>(Ul);
    k_agg<<<B_N * T_T, 256>>>(x, Wc, bc, bias, out);
}